// round 1
// baseline (speedup 1.0000x reference)
#include <cuda_runtime.h>
#include <cuda_bf16.h>

// Problem constants (fixed by reference):
//   g: (32, 16, 2048, 3) fp32, ar_phi: (3,3), ar_eta: (3,), ar_c: (3,)
//   P=3, KMAX=5 (11 windings), output: (32,) fp32
#define N_MC      32
#define N_SAMP    16
#define N_ROWS    (N_MC * N_SAMP)   // 512
#define T_LEN     2048
#define DDIM      3
#define TPRIME    2044               // T - 1 - P
#define ROW_ELEMS (T_LEN * DDIM)     // 6144 floats per (m,s) row
#define BLOCK     256

#define PI_F      3.14159265358979323846f
#define TWO_PI_F  6.28318530717958647693f
#define INV_2PI_F 0.15915494309189533577f

// Deterministic scratch: one double partial per (m,s) row. Fully overwritten
// every launch; no allocation, no atomics.
__device__ double g_row_partial[N_ROWS];

// Torus logmap in fp32, matching jnp.mod(x+pi, 2pi) - pi (floor-mod).
__device__ __forceinline__ float wrapf(float x) {
    float y = x + PI_F;
    float q = floorf(y * INV_2PI_F);
    return fmaf(-q, TWO_PI_F, y) - PI_F;
}

__global__ __launch_bounds__(BLOCK)
void arp_row_kernel(const float* __restrict__ g,
                    const float* __restrict__ ar_phi,
                    const float* __restrict__ ar_eta,
                    const float* __restrict__ ar_c) {
    __shared__ float sg[ROW_ELEMS];
    __shared__ float sred[DDIM][BLOCK / 32];

    const int row = blockIdx.x;

    // Coalesced stage of this row (24.6 KB) into SMEM via float4.
    const float4* g4 = reinterpret_cast<const float4*>(g + (size_t)row * ROW_ELEMS);
    float4* s4 = reinterpret_cast<float4*>(sg);
#pragma unroll
    for (int i = threadIdx.x; i < ROW_ELEMS / 4; i += BLOCK) s4[i] = g4[i];

    // Small params (L1/L2 cached broadcasts).
    float ph[DDIM][3], cc[DDIM];
#pragma unroll
    for (int d = 0; d < DDIM; d++) {
        ph[d][0] = ar_phi[d * 3 + 0];
        ph[d][1] = ar_phi[d * 3 + 1];
        ph[d][2] = ar_phi[d * 3 + 2];
        cc[d] = ar_c[d];
    }
    __syncthreads();

    // dy[t,d] = dx[t+3,d] - (phi[d,0]*dx[t+2,d] + phi[d,1]*dx[t+1,d] + phi[d,2]*dx[t,d])
    // where dx[a,d] = wrap(g[a+1,d] - g[a,d]).  Accumulate per-dim sum of u^2.
    float acc[DDIM] = {0.f, 0.f, 0.f};
    for (int t = threadIdx.x; t < TPRIME; t += BLOCK) {
#pragma unroll
        for (int d = 0; d < DDIM; d++) {
            const float* p = sg + t * DDIM + d;  // stride-3 word access: conflict-free
            float a0 = p[0], a1 = p[3], a2 = p[6], a3 = p[9], a4 = p[12];
            float x0 = wrapf(a1 - a0);
            float x1 = wrapf(a2 - a1);
            float x2 = wrapf(a3 - a2);
            float x3 = wrapf(a4 - a3);
            float dyv = x3 - (ph[d][0] * x2 + ph[d][1] * x1 + ph[d][2] * x0);
            float u = dyv - cc[d];
            acc[d] = fmaf(u, u, acc[d]);
        }
    }

    // Warp reduce, then cross-warp reduce in SMEM.
#pragma unroll
    for (int off = 16; off; off >>= 1) {
#pragma unroll
        for (int d = 0; d < DDIM; d++)
            acc[d] += __shfl_xor_sync(0xffffffffu, acc[d], off);
    }
    const int lane = threadIdx.x & 31;
    const int warp = threadIdx.x >> 5;
    if (lane == 0) {
#pragma unroll
        for (int d = 0; d < DDIM; d++) sred[d][warp] = acc[d];
    }
    __syncthreads();

    if (threadIdx.x == 0) {
        double part = 0.0;
#pragma unroll
        for (int d = 0; d < DDIM; d++) {
            double S = 0.0;
#pragma unroll
            for (int w = 0; w < BLOCK / 32; w++) S += (double)sred[d][w];
            double e = (double)ar_eta[d];
            double var = e * e;                  // scale^2 = eta^2
            part += -5.5 * S / var;              // sum over K windings of quadratic term
        }
        g_row_partial[row] = part;
    }
}

__global__ void arp_final_kernel(const float* __restrict__ ar_eta,
                                 float* __restrict__ out) {
    int m = threadIdx.x;
    if (m >= N_MC) return;

    // Closed-form constant per (t, sample):
    //   sum_d [ -220*pi^2/s_d^2 - 11*log(s_d) - 5.5*log(2*pi) ]
    double C = 0.0;
#pragma unroll
    for (int d = 0; d < DDIM; d++) {
        double e = fabs((double)ar_eta[d]);  // scale = sqrt(eta^2) = |eta|
        double pi = 3.14159265358979323846;
        C += -220.0 * pi * pi / (e * e) - 11.0 * log(e) - 5.5 * log(2.0 * pi);
    }

    double acc = 0.0;
#pragma unroll
    for (int s = 0; s < N_SAMP; s++) acc += g_row_partial[m * N_SAMP + s];
    acc += (double)N_SAMP * (double)TPRIME * C;

    out[m] = (float)acc;
}

extern "C" void kernel_launch(void* const* d_in, const int* in_sizes, int n_in,
                              void* d_out, int out_size) {
    const float* g      = (const float*)d_in[0];
    const float* ar_phi = (const float*)d_in[1];
    const float* ar_eta = (const float*)d_in[2];
    const float* ar_c   = (const float*)d_in[3];
    float* out = (float*)d_out;

    arp_row_kernel<<<N_ROWS, BLOCK>>>(g, ar_phi, ar_eta, ar_c);
    arp_final_kernel<<<1, 32>>>(ar_eta, out);
}

// round 2
// speedup vs baseline: 1.0980x; 1.0980x over previous
#include <cuda_runtime.h>
#include <cuda_bf16.h>

// Problem constants (fixed by reference):
//   g: (32, 16, 2048, 3) fp32, ar_phi: (3,3), ar_eta: (3,), ar_c: (3,)
//   P=3, KMAX=5 (11 windings), output: (32,) fp32
#define N_MC      32
#define N_SAMP    16
#define N_ROWS    (N_MC * N_SAMP)   // 512
#define T_LEN     2048
#define DDIM      3
#define TPRIME    2044               // T - 1 - P
#define ROW_ELEMS (T_LEN * DDIM)     // 6144 floats per (m,s) row
#define BLOCK     256
#define CHUNK     8                  // t-outputs per thread (256*8 = 2048 >= 2044)
#define SKEWLEN   (T_LEN + (T_LEN >> 3))   // 2304 floats per dim (skewed)

#define PI_F      3.14159265358979323846f
#define TWO_PI_F  6.28318530717958647693f
#define INV_2PI_F 0.15915494309189533577f

// Deterministic scratch: one double partial per (m,s) row, fully overwritten
// each launch. Ticket counter is module-init 0 and reset to 0 by the last
// block every launch, so graph replays are deterministic. No allocation.
__device__ double g_row_partial[N_ROWS];
__device__ unsigned int g_ticket = 0;

// Torus logmap in fp32, matching jnp.mod(x+pi, 2pi) - pi (floor-mod).
__device__ __forceinline__ float wrapf(float x) {
    float y = x + PI_F;
    float q = floorf(y * INV_2PI_F);
    return fmaf(-q, TWO_PI_F, y) - PI_F;
}

// Skewed index: lane-to-lane stride becomes 9 words (odd) -> conflict-free.
__device__ __forceinline__ int skew(int t) { return t + (t >> 3); }

__global__ __launch_bounds__(BLOCK)
void arp_fused_kernel(const float* __restrict__ g,
                      const float* __restrict__ ar_phi,
                      const float* __restrict__ ar_eta,
                      const float* __restrict__ ar_c,
                      float* __restrict__ out) {
    __shared__ float sd[DDIM][SKEWLEN];
    __shared__ float sred[DDIM][BLOCK / 32];
    __shared__ unsigned int s_last;

    const int row = blockIdx.x;
    const int tid = threadIdx.x;

    // ---- Stage this row (24.6 KB) into per-dim skewed SMEM, float4 global loads.
    const float4* g4 = reinterpret_cast<const float4*>(g + (size_t)row * ROW_ELEMS);
#pragma unroll
    for (int k = 0; k < ROW_ELEMS / 4 / BLOCK; k++) {      // 6 iterations
        int i = tid + k * BLOCK;
        float4 v = g4[i];
        int b = 4 * i;
        sd[(b + 0) % 3][skew((b + 0) / 3)] = v.x;
        sd[(b + 1) % 3][skew((b + 1) / 3)] = v.y;
        sd[(b + 2) % 3][skew((b + 2) / 3)] = v.z;
        sd[(b + 3) % 3][skew((b + 3) / 3)] = v.w;
    }

    // Small params (broadcast loads).
    float ph[DDIM][3], cc[DDIM];
#pragma unroll
    for (int d = 0; d < DDIM; d++) {
        ph[d][0] = ar_phi[d * 3 + 0];
        ph[d][1] = ar_phi[d * 3 + 1];
        ph[d][2] = ar_phi[d * 3 + 2];
        cc[d] = ar_c[d];
    }
    __syncthreads();

    // ---- Chunked AR(3) on wrapped diffs: thread handles t in [t0, t0+8).
    // Needs angles t0..t0+11, dx t0..t0+10; each dx computed ONCE.
    const int t0 = tid * CHUNK;
    float acc[DDIM];
#pragma unroll
    for (int d = 0; d < DDIM; d++) {
        float a[CHUNK + 4];
#pragma unroll
        for (int j = 0; j < CHUNK + 4; j++) {
            int tt = t0 + j;
            if (tt > T_LEN - 1) tt = T_LEN - 1;   // clamp (only tid 255 tail)
            a[j] = sd[d][skew(tt)];
        }
        float dx[CHUNK + 3];
#pragma unroll
        for (int j = 0; j < CHUNK + 3; j++) dx[j] = wrapf(a[j + 1] - a[j]);

        float s = 0.f;
#pragma unroll
        for (int j = 0; j < CHUNK; j++) {
            float dyv = dx[j + 3] - (ph[d][0] * dx[j + 2]
                                   + ph[d][1] * dx[j + 1]
                                   + ph[d][2] * dx[j]);
            float u = dyv - cc[d];
            if (t0 + j < TPRIME) s = fmaf(u, u, s);
        }
        acc[d] = s;
    }

    // ---- Warp reduce, cross-warp reduce.
#pragma unroll
    for (int off = 16; off; off >>= 1)
#pragma unroll
        for (int d = 0; d < DDIM; d++)
            acc[d] += __shfl_xor_sync(0xffffffffu, acc[d], off);

    const int lane = tid & 31;
    const int warp = tid >> 5;
    if (lane == 0)
#pragma unroll
        for (int d = 0; d < DDIM; d++) sred[d][warp] = acc[d];
    __syncthreads();

    if (tid == 0) {
        double part = 0.0;
#pragma unroll
        for (int d = 0; d < DDIM; d++) {
            double S = 0.0;
#pragma unroll
            for (int w = 0; w < BLOCK / 32; w++) S += (double)sred[d][w];
            double e = (double)ar_eta[d];
            part += -5.5 * S / (e * e);
        }
        g_row_partial[row] = part;
        __threadfence();
        unsigned int t = atomicAdd(&g_ticket, 1u);
        s_last = (t == N_ROWS - 1) ? 1u : 0u;
    }
    __syncthreads();

    // ---- Last-arriving block: deterministic final fold + closed-form constant.
    if (s_last) {
        __threadfence();
        if (tid < N_MC) {
            const double pi = 3.14159265358979323846;
            double C = 0.0;
#pragma unroll
            for (int d = 0; d < DDIM; d++) {
                double e = fabs((double)ar_eta[d]);   // scale = sqrt(eta^2)
                C += -220.0 * pi * pi / (e * e) - 11.0 * log(e)
                     - 5.5 * log(2.0 * pi);
            }
            double accm = 0.0;
#pragma unroll
            for (int s = 0; s < N_SAMP; s++)
                accm += g_row_partial[tid * N_SAMP + s];
            accm += (double)N_SAMP * (double)TPRIME * C;
            out[tid] = (float)accm;
        }
        if (tid == 0) atomicExch(&g_ticket, 0u);      // reset for next replay
    }
}

extern "C" void kernel_launch(void* const* d_in, const int* in_sizes, int n_in,
                              void* d_out, int out_size) {
    const float* g      = (const float*)d_in[0];
    const float* ar_phi = (const float*)d_in[1];
    const float* ar_eta = (const float*)d_in[2];
    const float* ar_c   = (const float*)d_in[3];
    float* out = (float*)d_out;

    arp_fused_kernel<<<N_ROWS, BLOCK>>>(g, ar_phi, ar_eta, ar_c, out);
}

// round 3
// speedup vs baseline: 1.1322x; 1.0311x over previous
#include <cuda_runtime.h>
#include <cuda_bf16.h>

// Problem constants (fixed by reference):
//   g: (32, 16, 2048, 3) fp32, ar_phi: (3,3), ar_eta: (3,), ar_c: (3,)
//   P=3, KMAX=5 (11 windings), output: (32,) fp32
#define N_MC      32
#define N_SAMP    16
#define N_ROWS    (N_MC * N_SAMP)       // 512
#define T_LEN     2048
#define TPRIME    2044                   // T - 1 - P
#define ROW_ELEMS (T_LEN * 3)            // 6144 floats
#define ROW_VEC4  (ROW_ELEMS / 4)        // 1536 float4s per row

#define BLOCKS_PER_ROW 2
#define GRID      (N_ROWS * BLOCKS_PER_ROW)  // 1024
#define BLOCK     128
#define CHUNK     8                      // outputs per thread (128*8 = 1024 per half-row)
#define HALF_T    1024                   // t-outputs covered per block

#define PI_F      3.14159265358979323846f
#define TWO_PI_F  6.28318530717958647693f
#define INV_2PI_F 0.15915494309189533577f

// Deterministic scratch: per-block double partials, fully overwritten each
// launch. Ticket counter reset to 0 by the last block -> replay-deterministic.
__device__ double g_partial[GRID];
__device__ unsigned int g_ticket = 0;

// Torus logmap in fp32, matching jnp.mod(x+pi, 2pi) - pi (floor-mod).
__device__ __forceinline__ float wrapf(float x) {
    float y = x + PI_F;
    float q = floorf(y * INV_2PI_F);
    return fmaf(-q, TWO_PI_F, y) - PI_F;
}

__global__ __launch_bounds__(BLOCK)
void arp_fused_kernel(const float* __restrict__ g,
                      const float* __restrict__ ar_phi,
                      const float* __restrict__ ar_eta,
                      const float* __restrict__ ar_c,
                      float* __restrict__ out) {
    __shared__ float sred[3][BLOCK / 32];
    __shared__ unsigned int s_last;

    const int blk  = blockIdx.x;
    const int row  = blk >> 1;            // (m*16 + s)
    const int half = blk & 1;
    const int tid  = threadIdx.x;
    const int t0   = half * HALF_T + tid * CHUNK;

    // Small params (L1-cached broadcast loads).
    float ph[3][3], cc[3];
#pragma unroll
    for (int d = 0; d < 3; d++) {
        ph[d][0] = __ldg(&ar_phi[d * 3 + 0]);
        ph[d][1] = __ldg(&ar_phi[d * 3 + 1]);
        ph[d][2] = __ldg(&ar_phi[d * 3 + 2]);
        cc[d]    = __ldg(&ar_c[d]);
    }

    // ---- Direct vectorized load: angles t0..t0+11, all 3 dims = 36 floats
    // = 9 consecutive float4s (3*t0 divisible by 4 since t0 % 8 == 0).
    // Warp footprint is contiguous -> fully coalesced sectors.
    const float4* g4 = reinterpret_cast<const float4*>(g) + (size_t)row * ROW_VEC4;
    const int base = (3 * t0) >> 2;
    float f[36];
#pragma unroll
    for (int k = 0; k < 9; k++) {
        int idx = base + k;
        if (idx > ROW_VEC4 - 1) idx = ROW_VEC4 - 1;   // tail clamp (unused data)
        float4 v = __ldg(&g4[idx]);
        f[4 * k + 0] = v.x; f[4 * k + 1] = v.y;
        f[4 * k + 2] = v.z; f[4 * k + 3] = v.w;
    }

    // ---- AR(3) on wrapped first-diffs, each dx computed exactly once.
    float acc[3];
#pragma unroll
    for (int d = 0; d < 3; d++) {
        float dx[CHUNK + 3];
#pragma unroll
        for (int j = 0; j < CHUNK + 3; j++)
            dx[j] = wrapf(f[3 * (j + 1) + d] - f[3 * j + d]);

        float s = 0.f;
#pragma unroll
        for (int j = 0; j < CHUNK; j++) {
            float dyv = dx[j + 3] - (ph[d][0] * dx[j + 2]
                                   + ph[d][1] * dx[j + 1]
                                   + ph[d][2] * dx[j]);
            float u = dyv - cc[d];
            if (t0 + j < TPRIME) s = fmaf(u, u, s);
        }
        acc[d] = s;
    }

    // ---- Warp reduce, then 4-warp fold.
#pragma unroll
    for (int off = 16; off; off >>= 1)
#pragma unroll
        for (int d = 0; d < 3; d++)
            acc[d] += __shfl_xor_sync(0xffffffffu, acc[d], off);

    const int lane = tid & 31;
    const int warp = tid >> 5;
    if (lane == 0)
#pragma unroll
        for (int d = 0; d < 3; d++) sred[d][warp] = acc[d];
    __syncthreads();

    if (tid == 0) {
        double part = 0.0;
#pragma unroll
        for (int d = 0; d < 3; d++) {
            double S = (double)sred[d][0] + (double)sred[d][1]
                     + (double)sred[d][2] + (double)sred[d][3];
            double e = (double)ar_eta[d];
            part += -5.5 * S / (e * e);
        }
        g_partial[blk] = part;
        __threadfence();
        unsigned int t = atomicAdd(&g_ticket, 1u);
        s_last = (t == GRID - 1) ? 1u : 0u;
    }
    __syncthreads();

    // ---- Last-arriving block: deterministic final fold + closed-form constant.
    //   sum_k in [-5,5] of the winding log-density collapses to
    //   -5.5*u^2/var - 220*pi^2/var - 11*log(scale) - 5.5*log(2*pi) per (t,d).
    if (s_last) {
        __threadfence();
        if (tid < N_MC) {
            const double pi = 3.14159265358979323846;
            double C = 0.0;
#pragma unroll
            for (int d = 0; d < 3; d++) {
                double e = fabs((double)ar_eta[d]);   // scale = sqrt(eta^2)
                C += -220.0 * pi * pi / (e * e) - 11.0 * log(e)
                     - 5.5 * log(2.0 * pi);
            }
            double accm = 0.0;
#pragma unroll
            for (int s = 0; s < N_SAMP * BLOCKS_PER_ROW; s++)
                accm += g_partial[tid * (N_SAMP * BLOCKS_PER_ROW) + s];
            accm += (double)N_SAMP * (double)TPRIME * C;
            out[tid] = (float)accm;
        }
        if (tid == 0) atomicExch(&g_ticket, 0u);      // reset for next replay
    }
}

extern "C" void kernel_launch(void* const* d_in, const int* in_sizes, int n_in,
                              void* d_out, int out_size) {
    const float* g      = (const float*)d_in[0];
    const float* ar_phi = (const float*)d_in[1];
    const float* ar_eta = (const float*)d_in[2];
    const float* ar_c   = (const float*)d_in[3];
    float* out = (float*)d_out;

    arp_fused_kernel<<<GRID, BLOCK>>>(g, ar_phi, ar_eta, ar_c, out);
}

// round 4
// speedup vs baseline: 2.6765x; 2.3640x over previous
#include <cuda_runtime.h>
#include <cuda_bf16.h>
#include <cstdint>

// Problem constants (fixed by reference):
//   g: (32, 16, 2048, 3) fp32, ar_phi: (3,3), ar_eta: (3,), ar_c: (3,)
//   P=3, KMAX=5 (11 windings), output: (32,) fp32
#define N_MC      32
#define N_SAMP    16
#define T_LEN     2048
#define TPRIME    2044                   // T - 1 - P
#define ROW_ELEMS (T_LEN * 3)            // 6144 floats
#define ROW_VEC4  (ROW_ELEMS / 4)        // 1536 float4s per row

#define CLUSTER   8                      // CTAs per cluster = per output m
#define SPC       2                      // samples per CTA (8*2 = 16 = N_SAMP)
#define GRID      (N_MC * CLUSTER)       // 256 CTAs, single wave
#define BLOCK     256
#define CHUNK     8                      // t-outputs per thread per sample

#define PI_F      3.14159265358979323846f
#define TWO_PI_F  6.28318530717958647693f
#define INV_2PI_F 0.15915494309189533577f

// Torus logmap in fp32, matching jnp.mod(x+pi, 2pi) - pi (floor-mod).
__device__ __forceinline__ float wrapf(float x) {
    float y = x + PI_F;
    float q = floorf(y * INV_2PI_F);
    return fmaf(-q, TWO_PI_F, y) - PI_F;
}

__device__ __forceinline__ uint32_t smem_u32(const void* p) {
    uint32_t a;
    asm("{ .reg .u64 t; cvta.to.shared.u64 t, %1; cvt.u32.u64 %0, t; }"
        : "=r"(a) : "l"(p));
    return a;
}

__global__ __launch_bounds__(BLOCK) __cluster_dims__(CLUSTER, 1, 1)
void arp_cluster_kernel(const float* __restrict__ g,
                        const float* __restrict__ ar_phi,
                        const float* __restrict__ ar_eta,
                        const float* __restrict__ ar_c,
                        float* __restrict__ out) {
    __shared__ float sred[3][BLOCK / 32];
    __shared__ float slots[CLUSTER][3];   // leader CTA collects per-rank sums here

    const int tid = threadIdx.x;
    const int m   = blockIdx.x / CLUSTER;
    uint32_t rank;
    asm("mov.u32 %0, %%cluster_ctarank;" : "=r"(rank));

    // Small params (L1-cached broadcast loads).
    float ph[3][3], cc[3];
#pragma unroll
    for (int d = 0; d < 3; d++) {
        ph[d][0] = __ldg(&ar_phi[d * 3 + 0]);
        ph[d][1] = __ldg(&ar_phi[d * 3 + 1]);
        ph[d][2] = __ldg(&ar_phi[d * 3 + 2]);
        cc[d]    = __ldg(&ar_c[d]);
    }

    const int t0   = tid * CHUNK;
    const int base = (3 * t0) >> 2;       // 3*t0 divisible by 4 (t0 % 8 == 0)

    // ---- Two sample-rows per CTA: direct vectorized loads, AR(3) on wrapped
    // first-diffs (each dx computed exactly once), fp32 accumulation.
    float acc[3] = {0.f, 0.f, 0.f};
#pragma unroll
    for (int s = 0; s < SPC; s++) {
        const int row = m * N_SAMP + (int)rank * SPC + s;
        const float4* g4 = reinterpret_cast<const float4*>(g)
                         + (size_t)row * ROW_VEC4;
        float f[36];
#pragma unroll
        for (int k = 0; k < 9; k++) {
            int idx = base + k;
            if (idx > ROW_VEC4 - 1) idx = ROW_VEC4 - 1;   // tail clamp (unused)
            float4 v = __ldg(&g4[idx]);
            f[4 * k + 0] = v.x; f[4 * k + 1] = v.y;
            f[4 * k + 2] = v.z; f[4 * k + 3] = v.w;
        }
#pragma unroll
        for (int d = 0; d < 3; d++) {
            float dx[CHUNK + 3];
#pragma unroll
            for (int j = 0; j < CHUNK + 3; j++)
                dx[j] = wrapf(f[3 * (j + 1) + d] - f[3 * j + d]);
            float ss = 0.f;
#pragma unroll
            for (int j = 0; j < CHUNK; j++) {
                float dyv = dx[j + 3] - (ph[d][0] * dx[j + 2]
                                       + ph[d][1] * dx[j + 1]
                                       + ph[d][2] * dx[j]);
                float u = dyv - cc[d];
                if (t0 + j < TPRIME) ss = fmaf(u, u, ss);
            }
            acc[d] += ss;
        }
    }

    // ---- Warp reduce, then 8-warp fold.
#pragma unroll
    for (int off = 16; off; off >>= 1)
#pragma unroll
        for (int d = 0; d < 3; d++)
            acc[d] += __shfl_xor_sync(0xffffffffu, acc[d], off);

    const int lane = tid & 31;
    const int warp = tid >> 5;
    if (lane == 0)
#pragma unroll
        for (int d = 0; d < 3; d++) sred[d][warp] = acc[d];
    __syncthreads();

    // ---- tid0 pushes this CTA's 3 sums into the LEADER CTA's slots via DSMEM.
    if (tid == 0) {
        float S[3];
#pragma unroll
        for (int d = 0; d < 3; d++) {
            float v = sred[d][0];
#pragma unroll
            for (int w = 1; w < BLOCK / 32; w++) v += sred[d][w];
            S[d] = v;
        }
        uint32_t laddr = smem_u32(&slots[rank][0]);   // same layout in every CTA
        uint32_t raddr;
        asm volatile("mapa.shared::cluster.u32 %0, %1, %2;"
                     : "=r"(raddr) : "r"(laddr), "r"(0u));   // -> leader (rank 0)
#pragma unroll
        for (int d = 0; d < 3; d++)
            asm volatile("st.shared::cluster.f32 [%0], %1;"
                         :: "r"(raddr + 4u * d), "f"(S[d]) : "memory");
    }

    // Cluster barrier: release DSMEM stores, then leader may read.
    asm volatile("barrier.cluster.arrive.aligned;" ::: "memory");
    asm volatile("barrier.cluster.wait.aligned;" ::: "memory");

    // ---- Leader CTA: fold 8 ranks + closed-form winding constant, write out[m].
    //   sum_{k=-5..5} winding log-density collapses (sum k = 0, sum k^2 = 110) to
    //   -5.5*u^2/var - 220*pi^2/var - 11*log(scale) - 5.5*log(2*pi) per (t,d).
    // fp32 throughout: abs error ~1e4 vs tolerance ~8.5e7.
    if (rank == 0 && tid == 0) {
        float res = 0.f;
#pragma unroll
        for (int d = 0; d < 3; d++) {
            float Sd = 0.f;
#pragma unroll
            for (int r = 0; r < CLUSTER; r++) Sd += slots[r][d];
            float e   = fabsf(ar_eta[d]);            // scale = sqrt(eta^2)
            float var = e * e;
            float C = -220.f * (PI_F * PI_F) / var - 11.f * logf(e)
                      - 5.5f * logf(TWO_PI_F);
            res += -5.5f * Sd / var + (float)(N_SAMP * TPRIME) * C;
        }
        out[m] = res;
    }
}

extern "C" void kernel_launch(void* const* d_in, const int* in_sizes, int n_in,
                              void* d_out, int out_size) {
    const float* g      = (const float*)d_in[0];
    const float* ar_phi = (const float*)d_in[1];
    const float* ar_eta = (const float*)d_in[2];
    const float* ar_c   = (const float*)d_in[3];
    float* out = (float*)d_out;

    arp_cluster_kernel<<<GRID, BLOCK>>>(g, ar_phi, ar_eta, ar_c, out);
}